// round 8
// baseline (speedup 1.0000x reference)
#include <cuda_runtime.h>
#include <cstdint>

// ---------------- device-global scratch ----------------
__device__ float g_W1t[512 * 512];      // W_hx^T [n][k] tf32
__device__ float g_Wht[512 * 512];      // W_hh^T [n][k] tf32
__device__ float g_Whh[512 * 512];      // W_hh fp32
__device__ float g_W2[512 * 512];       // W^2 fp32
__device__ float g_W4[512 * 512];       // W^4 fp32
__device__ float g_W8[512 * 512];       // W^8 fp32
__device__ float g_WCt[1024 * 512];     // [W4t ; W8t] tf32 [n][k]
__device__ float g_Wot[512 * 1024];     // W_o^T [n][k] tf32
__device__ float g_bh[512];
__device__ float g_bo[512];
__device__ float g_xr[(size_t)65536 * 512];     // tf32-rounded x [b*256+t][k]
__device__ float g_preh[(size_t)65536 * 512];   // [t*256+b][n] tf32-rounded
__device__ float g_Hall[(size_t)257 * 131072];  // [t][b][n] tf32-rounded
__device__ float g_hfin[131072];                // fp32 h_final
__device__ float g_Q0[(size_t)16384 * 512];
__device__ float g_Q1[(size_t)16384 * 512];
__device__ int g_cnt, g_phase;

// ---------------- helpers ----------------
__device__ __forceinline__ uint32_t smem_u32(const void* p) {
    uint32_t a;
    asm("{ .reg .u64 t; cvta.to.shared.u64 t, %1; cvt.u32.u64 %0, t; }" : "=r"(a) : "l"(p));
    return a;
}
__device__ __forceinline__ float rna_tf32(float x) {
    uint32_t r; asm("cvt.rna.tf32.f32 %0, %1;" : "=r"(r) : "f"(x));
    return __uint_as_float(r);
}
__device__ __forceinline__ int rowmap(int mode, int off, int m) {
    if (mode == 1) return ((m & 255) << 8) | (m >> 8);
    if (mode == 2) return ((m >> 8) << 10) + (off << 8) + (m & 255);
    if (mode == 3) return ((m >> 8) << 9) + (off << 8) + (m & 255);
    return m;
}
__device__ __forceinline__ void mma8(float* c, const uint32_t* a, const uint32_t* b) {
    asm volatile("mma.sync.aligned.m16n8k8.row.col.f32.tf32.tf32.f32 "
        "{%0,%1,%2,%3}, {%4,%5,%6,%7}, {%8,%9}, {%0,%1,%2,%3};"
        : "+f"(c[0]), "+f"(c[1]), "+f"(c[2]), "+f"(c[3])
        : "r"(a[0]), "r"(a[1]), "r"(a[2]), "r"(a[3]), "r"(b[0]), "r"(b[1]));
}
#define CP16(dst, src) asm volatile("cp.async.cg.shared.global [%0], [%1], 16;" :: "r"(dst), "l"(src))

// ---------------- prep ----------------
__global__ void prep_kernel(const float* __restrict__ Wh, const float* __restrict__ bh,
                            const float* __restrict__ Wo, const float* __restrict__ bo,
                            const float* __restrict__ h0) {
    int i = blockIdx.x * blockDim.x + threadIdx.x;
    if (i == 0) { g_cnt = 0; g_phase = 0; }
    if (i < 524288) {
        int k = i >> 9, n = i & 511;
        g_Wot[n * 1024 + k] = rna_tf32(Wo[i]);
    }
    if (i < 262144) {
        int k = i >> 9, n = i & 511;
        g_W1t[n * 512 + k] = rna_tf32(Wh[i]);
        float w = Wh[262144 + i];
        g_Whh[i] = w;
        g_Wht[n * 512 + k] = rna_tf32(w);
    }
    if (i < 131072) g_Hall[i] = rna_tf32(h0[i]);
    if (i < 512) { g_bh[i] = bh[i]; g_bo[i] = bo[i]; }
}

__global__ void xr_kernel(const float* __restrict__ x) {
    size_t i = ((size_t)blockIdx.x * blockDim.x + threadIdx.x) * 4;
    float4 v = *(const float4*)(x + i);
    v.x = rna_tf32(v.x); v.y = rna_tf32(v.y);
    v.z = rna_tf32(v.z); v.w = rna_tf32(v.w);
    *(float4*)(g_xr + i) = v;
}

// ------------- fp32 512^3 GEMM (squarings), 32x64 tile, grid(8,16) -------------
__global__ __launch_bounds__(256) void sq512(const float* __restrict__ A,
                                             const float* __restrict__ B,
                                             float* __restrict__ C,
                                             float* __restrict__ Ct) {
    __shared__ float As[16][36];
    __shared__ float Bs[16][64];
    const int tid = threadIdx.x;
    const int bm = blockIdx.y * 32, bn = blockIdx.x * 64;
    const int tx = tid & 15, ty = tid >> 4;
    const int ar = tid >> 3, ac2 = (tid & 7) * 2;
    const int br = tid >> 4, bc4 = (tid & 15) * 4;

    float acc[2][4] = {{0, 0, 0, 0}, {0, 0, 0, 0}};
    for (int k0 = 0; k0 < 512; k0 += 16) {
        float2 va = *(const float2*)(A + (size_t)(bm + ar) * 512 + k0 + ac2);
        float4 vb = *(const float4*)(B + (size_t)(k0 + br) * 512 + bn + bc4);
        __syncthreads();
        As[ac2 + 0][ar] = va.x;
        As[ac2 + 1][ar] = va.y;
        *(float4*)(&Bs[br][bc4]) = vb;
        __syncthreads();
#pragma unroll
        for (int kk = 0; kk < 16; kk++) {
            float a0 = As[kk][ty * 2 + 0], a1 = As[kk][ty * 2 + 1];
#pragma unroll
            for (int j = 0; j < 4; j++) {
                float b = Bs[kk][tx * 4 + j];
                acc[0][j] += a0 * b;
                acc[1][j] += a1 * b;
            }
        }
    }
#pragma unroll
    for (int i = 0; i < 2; i++) {
        int m = bm + ty * 2 + i;
        float4 v = {acc[i][0], acc[i][1], acc[i][2], acc[i][3]};
        *(float4*)(C + (size_t)m * 512 + bn + tx * 4) = v;
        if (Ct) {
#pragma unroll
            for (int j = 0; j < 4; j++)
                Ct[(size_t)(bn + tx * 4 + j) * 512 + m] = rna_tf32(acc[i][j]);
        }
    }
}

// ---------------- tf32 mma GEMM, 128x128 tile ----------------
// MODE 0: O = rna(A@Bt + bias)  K=512 | MODE 1: sigmoid, A=[xr|Hall-gather], K=1024
// MODE 2: O = rna(A@Bt + Add)   K=512
template <int MODE>
__global__ __launch_bounds__(256, 2) void mma_gemm(
    const float* __restrict__ A0, const float* __restrict__ A1, int amap, int aoff,
    const float* __restrict__ Add, int addmap, int addoff,
    float* __restrict__ O, int omap, int ooff,
    const float* __restrict__ Bt, const float* __restrict__ bias) {
    __shared__ float As[2][128][20];
    __shared__ float Bs[2][128][20];

    const int tid = threadIdx.x;
    const int lane = tid & 31;
    const int wid = tid >> 5;
    const int wm = (wid >> 2) * 64;
    const int wn = (wid & 3) * 32;
    const int bm = blockIdx.y * 128;
    const int bn = blockIdx.x * 128;
    const int KD = (MODE == 1) ? 1024 : 512;
    const int NIT = KD / 16;

    const int ar1 = tid >> 2, ac = (tid & 3) * 4;

    const float* aP[2];
    const float* aH[2];
#pragma unroll
    for (int h = 0; h < 2; h++) {
        int gm = bm + ar1 + h * 64;
        if (MODE == 1) {
            aP[h] = A0 + (size_t)gm * 512 + ac;
            aH[h] = A1 + (size_t)((((gm & 255) << 8) | (gm >> 8))) * 512 + ac;
        } else {
            aP[h] = A0 + (size_t)rowmap(amap, aoff, gm) * 512 + ac;
        }
    }
    const float* bP = Bt + (size_t)(bn + ar1) * KD + ac;

    auto issue = [&](int it) {
        const int k0 = it * 16;
        const int buf = it & 1;
#pragma unroll
        for (int h = 0; h < 2; h++) {
            const float* src = (MODE == 1 && k0 >= 512) ? aH[h] + (k0 - 512) : aP[h] + k0;
            CP16(smem_u32(&As[buf][ar1 + h * 64][ac]), src);
            CP16(smem_u32(&Bs[buf][ar1 + h * 64][ac]), bP + (size_t)h * 64 * KD + k0);
        }
        asm volatile("cp.async.commit_group;");
    };

    float acc[4][4][4];
#pragma unroll
    for (int a = 0; a < 4; a++)
#pragma unroll
        for (int b = 0; b < 4; b++)
#pragma unroll
            for (int c = 0; c < 4; c++) acc[a][b][c] = 0.f;

    issue(0);
    for (int it = 0; it < NIT; it++) {
        if (it + 1 < NIT) {
            issue(it + 1);
            asm volatile("cp.async.wait_group 1;");
        } else {
            asm volatile("cp.async.wait_group 0;");
        }
        __syncthreads();
        const float(*Asb)[20] = As[it & 1];
        const float(*Bsb)[20] = Bs[it & 1];
#pragma unroll
        for (int kk = 0; kk < 2; kk++) {
            const int kf = kk * 8 + (lane & 3);
            uint32_t af[4][4], bf[4][2];
#pragma unroll
            for (int mf = 0; mf < 4; mf++) {
                int r = wm + mf * 16 + (lane >> 2);
                af[mf][0] = __float_as_uint(Asb[r][kf]);
                af[mf][1] = __float_as_uint(Asb[r + 8][kf]);
                af[mf][2] = __float_as_uint(Asb[r][kf + 4]);
                af[mf][3] = __float_as_uint(Asb[r + 8][kf + 4]);
            }
#pragma unroll
            for (int nf = 0; nf < 4; nf++) {
                int r = wn + nf * 8 + (lane >> 2);
                bf[nf][0] = __float_as_uint(Bsb[r][kf]);
                bf[nf][1] = __float_as_uint(Bsb[r][kf + 4]);
            }
#pragma unroll
            for (int mf = 0; mf < 4; mf++)
#pragma unroll
                for (int nf = 0; nf < 4; nf++) mma8(acc[mf][nf], af[mf], bf[nf]);
        }
        __syncthreads();
    }

#pragma unroll
    for (int mf = 0; mf < 4; mf++)
#pragma unroll
        for (int nf = 0; nf < 4; nf++) {
            int col = bn + wn + nf * 8 + (lane & 3) * 2;
#pragma unroll
            for (int h = 0; h < 2; h++) {
                int r = bm + wm + mf * 16 + (lane >> 2) + h * 8;
                float c0 = acc[mf][nf][h * 2 + 0];
                float c1 = acc[mf][nf][h * 2 + 1];
                float2 v;
                if (MODE == 2) {
                    const float* ap = Add + (size_t)rowmap(addmap, addoff, r) * 512 + col;
                    v.x = rna_tf32(c0 + ap[0]);
                    v.y = rna_tf32(c1 + ap[1]);
                } else if (MODE == 0) {
                    v.x = rna_tf32(c0 + bias[col]);
                    v.y = rna_tf32(c1 + bias[col + 1]);
                } else {
                    v.x = 1.f / (1.f + __expf(-(c0 + bias[col])));
                    v.y = 1.f / (1.f + __expf(-(c1 + bias[col + 1])));
                }
                *(float2*)(O + (size_t)rowmap(omap, ooff, r) * 512 + col) = v;
            }
        }
}

// ---------------- persistent tensor-core scan ----------------
// superstep k: C[256x1024] = Hall[8k] @ [W4t ; W8t]
//   left  half: Hall[8k+4] = rna(C_l + Q4[2k])
//   right half: Hall[8k+8] = rna(C_r + Q8[k]);  k==31 -> g_hfin fp32
__device__ __forceinline__ void gbar(int target) {
    __syncthreads();
    if (threadIdx.x == 0) {
        __threadfence();
        int old = atomicAdd(&g_cnt, 1);
        if (old == 63) {
            g_cnt = 0;
            __threadfence();
            atomicExch(&g_phase, target);
        } else {
            while (atomicAdd(&g_phase, 0) < target) {}
        }
    }
    __syncthreads();
}

__global__ __launch_bounds__(256) void scan_kernel(const float* __restrict__ q4,
                                                   const float* __restrict__ q8) {
    __shared__ float As[2][32][20];
    __shared__ float Bs[2][128][20];
    const int tid = threadIdx.x;
    const int lane = tid & 31;
    const int wid = tid >> 5;
    const int wm = (wid >> 2) * 16;
    const int wn = (wid & 3) * 32;
    const int bn = blockIdx.x * 128;    // over N=1024
    const int bm = blockIdx.y * 32;     // over M=256
    // A loaders: threads 0..127, 16B each (32 rows x 16 floats per buffer)
    const int aar = tid >> 2, aac = (tid & 3) * 4;
    const int br = tid >> 2, bc = (tid & 3) * 4;
    const float* bP = g_WCt + (size_t)(bn + br) * 512 + bc;

    for (int k = 0; k < 32; k++) {
        const float* hsrc = g_Hall + (size_t)(8 * k) * 131072;

        auto issue = [&](int it) {
            const int k0 = it * 16;
            const int buf = it & 1;
            if (tid < 128)
                CP16(smem_u32(&As[buf][aar][aac]), hsrc + (size_t)(bm + aar) * 512 + k0 + aac);
#pragma unroll
            for (int h = 0; h < 2; h++)
                CP16(smem_u32(&Bs[buf][br + h * 64][bc]), bP + (size_t)h * 64 * 512 + k0);
            asm volatile("cp.async.commit_group;");
        };

        float acc[4][4];
#pragma unroll
        for (int a = 0; a < 4; a++)
#pragma unroll
            for (int b = 0; b < 4; b++) acc[a][b] = 0.f;

        issue(0);
        for (int it = 0; it < 32; it++) {
            if (it + 1 < 32) {
                issue(it + 1);
                asm volatile("cp.async.wait_group 1;");
            } else {
                asm volatile("cp.async.wait_group 0;");
            }
            __syncthreads();
            const float(*Asb)[20] = As[it & 1];
            const float(*Bsb)[20] = Bs[it & 1];
#pragma unroll
            for (int kk = 0; kk < 2; kk++) {
                const int kf = kk * 8 + (lane & 3);
                uint32_t af[4], bf[4][2];
                int r = wm + (lane >> 2);
                af[0] = __float_as_uint(Asb[r][kf]);
                af[1] = __float_as_uint(Asb[r + 8][kf]);
                af[2] = __float_as_uint(Asb[r][kf + 4]);
                af[3] = __float_as_uint(Asb[r + 8][kf + 4]);
#pragma unroll
                for (int nf = 0; nf < 4; nf++) {
                    int rb = wn + nf * 8 + (lane >> 2);
                    bf[nf][0] = __float_as_uint(Bsb[rb][kf]);
                    bf[nf][1] = __float_as_uint(Bsb[rb][kf + 4]);
                }
#pragma unroll
                for (int nf = 0; nf < 4; nf++) mma8(acc[nf], af, bf[nf]);
            }
            __syncthreads();
        }

#pragma unroll
        for (int nf = 0; nf < 4; nf++) {
            int col = bn + wn + nf * 8 + (lane & 3) * 2;
#pragma unroll
            for (int h = 0; h < 2; h++) {
                int r = bm + wm + (lane >> 2) + h * 8;
                float c0 = acc[nf][h * 2 + 0];
                float c1 = acc[nf][h * 2 + 1];
                size_t off = (size_t)r * 512;
                if (bn < 512) {
                    const float* p = q4 + (size_t)(2 * k) * 131072 + off + col;
                    float2 v = {rna_tf32(c0 + p[0]), rna_tf32(c1 + p[1])};
                    *(float2*)(g_Hall + (size_t)(8 * k + 4) * 131072 + off + col) = v;
                } else {
                    int c2 = col - 512;
                    const float* p = q8 + (size_t)k * 131072 + off + c2;
                    float f0 = c0 + p[0], f1 = c1 + p[1];
                    float2 v = {rna_tf32(f0), rna_tf32(f1)};
                    *(float2*)(g_Hall + (size_t)(8 * k + 8) * 131072 + off + c2) = v;
                    if (k == 31) {
                        float2 w = {f0, f1};
                        *(float2*)(g_hfin + off + c2) = w;
                    }
                }
            }
        }
        gbar(k + 1);
    }
}

__global__ void final_kernel(float* __restrict__ out) {
    int i = blockIdx.x * blockDim.x + threadIdx.x;
    if (i < 131072) out[(size_t)33554432 + i] = g_hfin[i];
}

// ---------------- launch ----------------
extern "C" void kernel_launch(void* const* d_in, const int* in_sizes, int n_in,
                              void* d_out, int out_size) {
    const float* x  = (const float*)d_in[0];
    const float* h0 = (const float*)d_in[1];
    const float* Wh = (const float*)d_in[2];
    const float* bh = (const float*)d_in[3];
    const float* Wo = (const float*)d_in[4];
    const float* bo = (const float*)d_in[5];
    float* out = (float*)d_out;

    float *xr, *preh, *hall, *q0, *q1, *w1t, *wht, *whh, *w2, *w4, *w8, *wct, *wot, *bhp, *bop;
    cudaGetSymbolAddress((void**)&xr, g_xr);
    cudaGetSymbolAddress((void**)&preh, g_preh);
    cudaGetSymbolAddress((void**)&hall, g_Hall);
    cudaGetSymbolAddress((void**)&q0, g_Q0);
    cudaGetSymbolAddress((void**)&q1, g_Q1);
    cudaGetSymbolAddress((void**)&w1t, g_W1t);
    cudaGetSymbolAddress((void**)&wht, g_Wht);
    cudaGetSymbolAddress((void**)&whh, g_Whh);
    cudaGetSymbolAddress((void**)&w2, g_W2);
    cudaGetSymbolAddress((void**)&w4, g_W4);
    cudaGetSymbolAddress((void**)&w8, g_W8);
    cudaGetSymbolAddress((void**)&wct, g_WCt);
    cudaGetSymbolAddress((void**)&wot, g_Wot);
    cudaGetSymbolAddress((void**)&bhp, g_bh);
    cudaGetSymbolAddress((void**)&bop, g_bo);

    prep_kernel<<<2048, 256>>>(Wh, bh, Wo, bo, h0);
    xr_kernel<<<32768, 256>>>(x);
    sq512<<<dim3(8, 16), 256>>>(whh, whh, w2, nullptr);
    sq512<<<dim3(8, 16), 256>>>(w2, w2, w4, wct);             // W4 + W4t(tf32)
    sq512<<<dim3(8, 16), 256>>>(w4, w4, w8, wct + 262144);    // W8 + W8t(tf32)

    // G1: preh[t*256+b] = rna(xr[b][t] @ W_hx + b_h)
    mma_gemm<0><<<dim3(4, 512), 256>>>(xr, nullptr, 1, 0, nullptr, 0, 0,
                                       preh, 0, 0, w1t, bhp);
    // Horner chunks of 4 -> Q4 (q0)
    mma_gemm<2><<<dim3(4, 128), 256>>>(preh, nullptr, 2, 0, preh, 2, 1, q0, 0, 0, wht, nullptr);
    mma_gemm<2><<<dim3(4, 128), 256>>>(q0, nullptr, 0, 0, preh, 2, 2, q1, 0, 0, wht, nullptr);
    mma_gemm<2><<<dim3(4, 128), 256>>>(q1, nullptr, 0, 0, preh, 2, 3, q0, 0, 0, wht, nullptr);
    // Q8[k] = Q4[2k]@W4 + Q4[2k+1] -> q1  (W4t = first half of WCt)
    mma_gemm<2><<<dim3(4, 64), 256>>>(q0, nullptr, 3, 0, q0, 3, 1, q1, 0, 0, wct, nullptr);
    // persistent tensor-core scan, 32 supersteps
    scan_kernel<<<dim3(8, 8), 256>>>(q0, q1);
    // interior recovery: Hall[4j+i] = rna(Hall[4j+i-1]@W + preh[4j+i-1])
    for (int i = 1; i <= 3; i++)
        mma_gemm<2><<<dim3(4, 128), 256>>>(hall, nullptr, 2, i - 1, preh, 2, i - 1,
                                           hall, 2, i, wht, nullptr);
    // G2: out[b*256+t] = sigmoid([xr | Hall[t]] @ W_o + b_o)
    mma_gemm<1><<<dim3(4, 512), 256>>>(xr, hall, 0, 0, nullptr, 0, 0,
                                       out, 0, 0, wot, bop);
    final_kernel<<<512, 256>>>(out);
}

// round 9
// speedup vs baseline: 1.1135x; 1.1135x over previous
#include <cuda_runtime.h>
#include <cstdint>

// ---------------- device-global scratch ----------------
__device__ float g_W1t[512 * 512];      // W_hx^T [n][k] tf32
__device__ float g_Wht[512 * 512];      // W_hh^T [n][k] tf32
__device__ float g_Whh[512 * 512];      // W_hh fp32
__device__ float g_W2[512 * 512];       // W^2 fp32
__device__ float g_W4[512 * 512];       // W^4 fp32
__device__ float g_W8[512 * 512];       // W^8 fp32
__device__ float g_WCt[1024 * 512];     // [W4t ; W8t] tf32 [n][k]
__device__ float g_Wot[512 * 1024];     // W_o^T [n][k] tf32
__device__ float g_bh[512];
__device__ float g_bo[512];
__device__ float g_xr[(size_t)65536 * 512];     // tf32-rounded x [b*256+t][k]
__device__ float g_preh[(size_t)65536 * 512];   // [t*256+b][n] tf32-rounded
__device__ float g_Hall[(size_t)257 * 131072];  // [t][b][n] tf32-rounded
__device__ float g_hfin[131072];                // fp32 h_final
__device__ float g_Q0[(size_t)16384 * 512];
__device__ float g_Q1[(size_t)16384 * 512];
__device__ int g_cnt, g_phase;

// ---------------- helpers ----------------
__device__ __forceinline__ uint32_t smem_u32(const void* p) {
    uint32_t a;
    asm("{ .reg .u64 t; cvta.to.shared.u64 t, %1; cvt.u32.u64 %0, t; }" : "=r"(a) : "l"(p));
    return a;
}
__device__ __forceinline__ float rna_tf32(float x) {
    uint32_t r; asm("cvt.rna.tf32.f32 %0, %1;" : "=r"(r) : "f"(x));
    return __uint_as_float(r);
}
__device__ __forceinline__ int rowmap(int mode, int off, int m) {
    if (mode == 1) return ((m & 255) << 8) | (m >> 8);
    if (mode == 2) return ((m >> 8) << 10) + (off << 8) + (m & 255);
    if (mode == 3) return ((m >> 8) << 9) + (off << 8) + (m & 255);
    return m;
}
__device__ __forceinline__ void mma8(float* c, const uint32_t* a, const uint32_t* b) {
    asm volatile("mma.sync.aligned.m16n8k8.row.col.f32.tf32.tf32.f32 "
        "{%0,%1,%2,%3}, {%4,%5,%6,%7}, {%8,%9}, {%0,%1,%2,%3};"
        : "+f"(c[0]), "+f"(c[1]), "+f"(c[2]), "+f"(c[3])
        : "r"(a[0]), "r"(a[1]), "r"(a[2]), "r"(a[3]), "r"(b[0]), "r"(b[1]));
}
#define CP16(dst, src) asm volatile("cp.async.cg.shared.global [%0], [%1], 16;" :: "r"(dst), "l"(src))
#define LDSM4(r0, r1, r2, r3, addr)                                              \
    asm volatile("ldmatrix.sync.aligned.m8n8.x4.shared.b16 {%0,%1,%2,%3}, [%4];" \
        : "=r"(r0), "=r"(r1), "=r"(r2), "=r"(r3) : "r"(addr))

// Fragment lane offsets for ldmatrix-based loading (smem row stride 20 floats):
// A tiles (a0..a3): row = ((lane>>3)&1)*8 + (lane&7), col = ((lane>>4)&1)*4
// B tiles (b0(2p),b1(2p),b0(2p+1),b1(2p+1)): row = ((lane>>4)&1)*8 + (lane&7),
//                                            col = ((lane>>3)&1)*4

// ---------------- prep ----------------
__global__ void prep_kernel(const float* __restrict__ Wh, const float* __restrict__ bh,
                            const float* __restrict__ Wo, const float* __restrict__ bo,
                            const float* __restrict__ h0) {
    int i = blockIdx.x * blockDim.x + threadIdx.x;
    if (i == 0) { g_cnt = 0; g_phase = 0; }
    if (i < 524288) {
        int k = i >> 9, n = i & 511;
        g_Wot[n * 1024 + k] = rna_tf32(Wo[i]);
    }
    if (i < 262144) {
        int k = i >> 9, n = i & 511;
        g_W1t[n * 512 + k] = rna_tf32(Wh[i]);
        float w = Wh[262144 + i];
        g_Whh[i] = w;
        g_Wht[n * 512 + k] = rna_tf32(w);
    }
    if (i < 131072) g_Hall[i] = rna_tf32(h0[i]);
    if (i < 512) { g_bh[i] = bh[i]; g_bo[i] = bo[i]; }
}

__global__ void xr_kernel(const float* __restrict__ x) {
    size_t i = ((size_t)blockIdx.x * blockDim.x + threadIdx.x) * 4;
    float4 v = *(const float4*)(x + i);
    v.x = rna_tf32(v.x); v.y = rna_tf32(v.y);
    v.z = rna_tf32(v.z); v.w = rna_tf32(v.w);
    *(float4*)(g_xr + i) = v;
}

// ------------- fp32 512^3 GEMM (squarings), 32x64 tile, grid(8,16) -------------
__global__ __launch_bounds__(256) void sq512(const float* __restrict__ A,
                                             const float* __restrict__ B,
                                             float* __restrict__ C,
                                             float* __restrict__ Ct) {
    __shared__ float As[16][36];
    __shared__ float Bs[16][64];
    const int tid = threadIdx.x;
    const int bm = blockIdx.y * 32, bn = blockIdx.x * 64;
    const int tx = tid & 15, ty = tid >> 4;
    const int ar = tid >> 3, ac2 = (tid & 7) * 2;
    const int br = tid >> 4, bc4 = (tid & 15) * 4;

    float acc[2][4] = {{0, 0, 0, 0}, {0, 0, 0, 0}};
    for (int k0 = 0; k0 < 512; k0 += 16) {
        float2 va = *(const float2*)(A + (size_t)(bm + ar) * 512 + k0 + ac2);
        float4 vb = *(const float4*)(B + (size_t)(k0 + br) * 512 + bn + bc4);
        __syncthreads();
        As[ac2 + 0][ar] = va.x;
        As[ac2 + 1][ar] = va.y;
        *(float4*)(&Bs[br][bc4]) = vb;
        __syncthreads();
#pragma unroll
        for (int kk = 0; kk < 16; kk++) {
            float a0 = As[kk][ty * 2 + 0], a1 = As[kk][ty * 2 + 1];
#pragma unroll
            for (int j = 0; j < 4; j++) {
                float b = Bs[kk][tx * 4 + j];
                acc[0][j] += a0 * b;
                acc[1][j] += a1 * b;
            }
        }
    }
#pragma unroll
    for (int i = 0; i < 2; i++) {
        int m = bm + ty * 2 + i;
        float4 v = {acc[i][0], acc[i][1], acc[i][2], acc[i][3]};
        *(float4*)(C + (size_t)m * 512 + bn + tx * 4) = v;
        if (Ct) {
#pragma unroll
            for (int j = 0; j < 4; j++)
                Ct[(size_t)(bn + tx * 4 + j) * 512 + m] = rna_tf32(acc[i][j]);
        }
    }
}

// ---------------- tf32 mma GEMM, 128x128 tile, ldmatrix fragments ----------------
// MODE 0: O = rna(A@Bt + bias)  K=512 | MODE 1: sigmoid, A=[xr|Hall-gather], K=1024
// MODE 2: O = rna(A@Bt + Add)   K=512
template <int MODE>
__global__ __launch_bounds__(256, 2) void mma_gemm(
    const float* __restrict__ A0, const float* __restrict__ A1, int amap, int aoff,
    const float* __restrict__ Add, int addmap, int addoff,
    float* __restrict__ O, int omap, int ooff,
    const float* __restrict__ Bt, const float* __restrict__ bias) {
    __shared__ float As[2][128][20];
    __shared__ float Bs[2][128][20];

    const int tid = threadIdx.x;
    const int lane = tid & 31;
    const int wid = tid >> 5;
    const int wm = (wid >> 2) * 64;
    const int wn = (wid & 3) * 32;
    const int bm = blockIdx.y * 128;
    const int bn = blockIdx.x * 128;
    const int KD = (MODE == 1) ? 1024 : 512;
    const int NIT = KD / 16;

    const int ar1 = tid >> 2, ac = (tid & 3) * 4;

    const float* aP[2];
    const float* aH[2];
#pragma unroll
    for (int h = 0; h < 2; h++) {
        int gm = bm + ar1 + h * 64;
        if (MODE == 1) {
            aP[h] = A0 + (size_t)gm * 512 + ac;
            aH[h] = A1 + (size_t)((((gm & 255) << 8) | (gm >> 8))) * 512 + ac;
        } else {
            aP[h] = A0 + (size_t)rowmap(amap, aoff, gm) * 512 + ac;
        }
    }
    const float* bP = Bt + (size_t)(bn + ar1) * KD + ac;

    auto issue = [&](int it) {
        const int k0 = it * 16;
        const int buf = it & 1;
#pragma unroll
        for (int h = 0; h < 2; h++) {
            const float* src = (MODE == 1 && k0 >= 512) ? aH[h] + (k0 - 512) : aP[h] + k0;
            CP16(smem_u32(&As[buf][ar1 + h * 64][ac]), src);
            CP16(smem_u32(&Bs[buf][ar1 + h * 64][ac]), bP + (size_t)h * 64 * KD + k0);
        }
        asm volatile("cp.async.commit_group;");
    };

    // ldmatrix lane-invariant bases
    const int rA = ((lane >> 3) & 1) * 8 + (lane & 7);
    const int cA = ((lane >> 4) & 1) * 4;
    const int rB = ((lane >> 4) & 1) * 8 + (lane & 7);
    const int cB = ((lane >> 3) & 1) * 4;
    uint32_t baseA[2], baseB[2];
    baseA[0] = smem_u32(&As[0][wm + rA][cA]);
    baseA[1] = smem_u32(&As[1][wm + rA][cA]);
    baseB[0] = smem_u32(&Bs[0][wn + rB][cB]);
    baseB[1] = smem_u32(&Bs[1][wn + rB][cB]);

    float acc[4][4][4];
#pragma unroll
    for (int a = 0; a < 4; a++)
#pragma unroll
        for (int b = 0; b < 4; b++)
#pragma unroll
            for (int c = 0; c < 4; c++) acc[a][b][c] = 0.f;

    issue(0);
    for (int it = 0; it < NIT; it++) {
        if (it + 1 < NIT) {
            issue(it + 1);
            asm volatile("cp.async.wait_group 1;");
        } else {
            asm volatile("cp.async.wait_group 0;");
        }
        __syncthreads();
        const int buf = it & 1;
#pragma unroll
        for (int kk = 0; kk < 2; kk++) {
            uint32_t af[4][4], bf[2][4];
#pragma unroll
            for (int mf = 0; mf < 4; mf++)
                LDSM4(af[mf][0], af[mf][1], af[mf][2], af[mf][3],
                      baseA[buf] + mf * 1280 + kk * 32);
#pragma unroll
            for (int p = 0; p < 2; p++)
                LDSM4(bf[p][0], bf[p][1], bf[p][2], bf[p][3],
                      baseB[buf] + p * 1280 + kk * 32);
#pragma unroll
            for (int mf = 0; mf < 4; mf++)
#pragma unroll
                for (int p = 0; p < 2; p++) {
                    mma8(acc[mf][2 * p + 0], af[mf], &bf[p][0]);
                    mma8(acc[mf][2 * p + 1], af[mf], &bf[p][2]);
                }
        }
        __syncthreads();
    }

#pragma unroll
    for (int mf = 0; mf < 4; mf++)
#pragma unroll
        for (int nf = 0; nf < 4; nf++) {
            int col = bn + wn + nf * 8 + (lane & 3) * 2;
#pragma unroll
            for (int h = 0; h < 2; h++) {
                int r = bm + wm + mf * 16 + (lane >> 2) + h * 8;
                float c0 = acc[mf][nf][h * 2 + 0];
                float c1 = acc[mf][nf][h * 2 + 1];
                float2 v;
                if (MODE == 2) {
                    const float* ap = Add + (size_t)rowmap(addmap, addoff, r) * 512 + col;
                    v.x = rna_tf32(c0 + ap[0]);
                    v.y = rna_tf32(c1 + ap[1]);
                } else if (MODE == 0) {
                    v.x = rna_tf32(c0 + bias[col]);
                    v.y = rna_tf32(c1 + bias[col + 1]);
                } else {
                    v.x = 1.f / (1.f + __expf(-(c0 + bias[col])));
                    v.y = 1.f / (1.f + __expf(-(c1 + bias[col + 1])));
                }
                *(float2*)(O + (size_t)rowmap(omap, ooff, r) * 512 + col) = v;
            }
        }
}

// ---------------- persistent tensor-core scan ----------------
// superstep k: C[256x1024] = Hall[8k] @ [W4t ; W8t]
//   left  half: Hall[8k+4] = rna(C_l + Q4[2k])
//   right half: Hall[8k+8] = rna(C_r + Q8[k]);  k==31 -> g_hfin fp32
__device__ __forceinline__ void gbar(int target) {
    __syncthreads();
    if (threadIdx.x == 0) {
        __threadfence();
        int old = atomicAdd(&g_cnt, 1);
        if (old == 63) {
            g_cnt = 0;
            __threadfence();
            atomicExch(&g_phase, target);
        } else {
            while (atomicAdd(&g_phase, 0) < target) {}
        }
    }
    __syncthreads();
}

__global__ __launch_bounds__(256) void scan_kernel(const float* __restrict__ q4,
                                                   const float* __restrict__ q8) {
    __shared__ float As[2][32][20];
    __shared__ float Bs[2][128][20];
    const int tid = threadIdx.x;
    const int lane = tid & 31;
    const int wid = tid >> 5;
    const int wm = (wid >> 2) * 16;
    const int wn = (wid & 3) * 32;
    const int bn = blockIdx.x * 128;    // over N=1024
    const int bm = blockIdx.y * 32;     // over M=256
    const int aar = tid >> 2, aac = (tid & 3) * 4;
    const int br = tid >> 2, bc = (tid & 3) * 4;
    const float* bP = g_WCt + (size_t)(bn + br) * 512 + bc;

    // ldmatrix bases
    const int rA = ((lane >> 3) & 1) * 8 + (lane & 7);
    const int cA = ((lane >> 4) & 1) * 4;
    const int rB = ((lane >> 4) & 1) * 8 + (lane & 7);
    const int cB = ((lane >> 3) & 1) * 4;
    uint32_t baseA[2], baseB[2];
    baseA[0] = smem_u32(&As[0][wm + rA][cA]);
    baseA[1] = smem_u32(&As[1][wm + rA][cA]);
    baseB[0] = smem_u32(&Bs[0][wn + rB][cB]);
    baseB[1] = smem_u32(&Bs[1][wn + rB][cB]);

    for (int k = 0; k < 32; k++) {
        const float* hsrc = g_Hall + (size_t)(8 * k) * 131072;

        auto issue = [&](int it) {
            const int k0 = it * 16;
            const int buf = it & 1;
            if (tid < 128)
                CP16(smem_u32(&As[buf][aar][aac]), hsrc + (size_t)(bm + aar) * 512 + k0 + aac);
#pragma unroll
            for (int h = 0; h < 2; h++)
                CP16(smem_u32(&Bs[buf][br + h * 64][bc]), bP + (size_t)h * 64 * 512 + k0);
            asm volatile("cp.async.commit_group;");
        };

        float acc[4][4];
#pragma unroll
        for (int a = 0; a < 4; a++)
#pragma unroll
            for (int b = 0; b < 4; b++) acc[a][b] = 0.f;

        issue(0);
        for (int it = 0; it < 32; it++) {
            if (it + 1 < 32) {
                issue(it + 1);
                asm volatile("cp.async.wait_group 1;");
            } else {
                asm volatile("cp.async.wait_group 0;");
            }
            __syncthreads();
            const int buf = it & 1;
#pragma unroll
            for (int kk = 0; kk < 2; kk++) {
                uint32_t af[4], bf[2][4];
                LDSM4(af[0], af[1], af[2], af[3], baseA[buf] + kk * 32);
#pragma unroll
                for (int p = 0; p < 2; p++)
                    LDSM4(bf[p][0], bf[p][1], bf[p][2], bf[p][3],
                          baseB[buf] + p * 1280 + kk * 32);
#pragma unroll
                for (int p = 0; p < 2; p++) {
                    mma8(acc[2 * p + 0], af, &bf[p][0]);
                    mma8(acc[2 * p + 1], af, &bf[p][2]);
                }
            }
            __syncthreads();
        }

#pragma unroll
        for (int nf = 0; nf < 4; nf++) {
            int col = bn + wn + nf * 8 + (lane & 3) * 2;
#pragma unroll
            for (int h = 0; h < 2; h++) {
                int r = bm + wm + (lane >> 2) + h * 8;
                float c0 = acc[nf][h * 2 + 0];
                float c1 = acc[nf][h * 2 + 1];
                size_t off = (size_t)r * 512;
                if (bn < 512) {
                    const float* p = q4 + (size_t)(2 * k) * 131072 + off + col;
                    float2 v = {rna_tf32(c0 + p[0]), rna_tf32(c1 + p[1])};
                    *(float2*)(g_Hall + (size_t)(8 * k + 4) * 131072 + off + col) = v;
                } else {
                    int c2 = col - 512;
                    const float* p = q8 + (size_t)k * 131072 + off + c2;
                    float f0 = c0 + p[0], f1 = c1 + p[1];
                    float2 v = {rna_tf32(f0), rna_tf32(f1)};
                    *(float2*)(g_Hall + (size_t)(8 * k + 8) * 131072 + off + c2) = v;
                    if (k == 31) {
                        float2 w = {f0, f1};
                        *(float2*)(g_hfin + off + c2) = w;
                    }
                }
            }
        }
        gbar(k + 1);
    }
}

__global__ void final_kernel(float* __restrict__ out) {
    int i = blockIdx.x * blockDim.x + threadIdx.x;
    if (i < 131072) out[(size_t)33554432 + i] = g_hfin[i];
}

// ---------------- launch ----------------
extern "C" void kernel_launch(void* const* d_in, const int* in_sizes, int n_in,
                              void* d_out, int out_size) {
    const float* x  = (const float*)d_in[0];
    const float* h0 = (const float*)d_in[1];
    const float* Wh = (const float*)d_in[2];
    const float* bh = (const float*)d_in[3];
    const float* Wo = (const float*)d_in[4];
    const float* bo = (const float*)d_in[5];
    float* out = (float*)d_out;

    float *xr, *preh, *hall, *q0, *q1, *w1t, *wht, *whh, *w2, *w4, *w8, *wct, *wot, *bhp, *bop;
    cudaGetSymbolAddress((void**)&xr, g_xr);
    cudaGetSymbolAddress((void**)&preh, g_preh);
    cudaGetSymbolAddress((void**)&hall, g_Hall);
    cudaGetSymbolAddress((void**)&q0, g_Q0);
    cudaGetSymbolAddress((void**)&q1, g_Q1);
    cudaGetSymbolAddress((void**)&w1t, g_W1t);
    cudaGetSymbolAddress((void**)&wht, g_Wht);
    cudaGetSymbolAddress((void**)&whh, g_Whh);
    cudaGetSymbolAddress((void**)&w2, g_W2);
    cudaGetSymbolAddress((void**)&w4, g_W4);
    cudaGetSymbolAddress((void**)&w8, g_W8);
    cudaGetSymbolAddress((void**)&wct, g_WCt);
    cudaGetSymbolAddress((void**)&wot, g_Wot);
    cudaGetSymbolAddress((void**)&bhp, g_bh);
    cudaGetSymbolAddress((void**)&bop, g_bo);

    prep_kernel<<<2048, 256>>>(Wh, bh, Wo, bo, h0);
    xr_kernel<<<32768, 256>>>(x);
    sq512<<<dim3(8, 16), 256>>>(whh, whh, w2, nullptr);
    sq512<<<dim3(8, 16), 256>>>(w2, w2, w4, wct);             // W4 + W4t(tf32)
    sq512<<<dim3(8, 16), 256>>>(w4, w4, w8, wct + 262144);    // W8 + W8t(tf32)

    // G1: preh[t*256+b] = rna(xr[b][t] @ W_hx + b_h)
    mma_gemm<0><<<dim3(4, 512), 256>>>(xr, nullptr, 1, 0, nullptr, 0, 0,
                                       preh, 0, 0, w1t, bhp);
    // Horner chunks of 4 -> Q4 (q0)
    mma_gemm<2><<<dim3(4, 128), 256>>>(preh, nullptr, 2, 0, preh, 2, 1, q0, 0, 0, wht, nullptr);
    mma_gemm<2><<<dim3(4, 128), 256>>>(q0, nullptr, 0, 0, preh, 2, 2, q1, 0, 0, wht, nullptr);
    mma_gemm<2><<<dim3(4, 128), 256>>>(q1, nullptr, 0, 0, preh, 2, 3, q0, 0, 0, wht, nullptr);
    // Q8[k] = Q4[2k]@W4 + Q4[2k+1] -> q1  (W4t = first half of WCt)
    mma_gemm<2><<<dim3(4, 64), 256>>>(q0, nullptr, 3, 0, q0, 3, 1, q1, 0, 0, wct, nullptr);
    // persistent tensor-core scan, 32 supersteps
    scan_kernel<<<dim3(8, 8), 256>>>(q0, q1);
    // interior recovery: Hall[4j+i] = rna(Hall[4j+i-1]@W + preh[4j+i-1])
    for (int i = 1; i <= 3; i++)
        mma_gemm<2><<<dim3(4, 128), 256>>>(hall, nullptr, 2, i - 1, preh, 2, i - 1,
                                           hall, 2, i, wht, nullptr);
    // G2: out[b*256+t] = sigmoid([xr | Hall[t]] @ W_o + b_o)
    mma_gemm<1><<<dim3(4, 512), 256>>>(xr, hall, 0, 0, nullptr, 0, 0,
                                       out, 0, 0, wot, bop);
    final_kernel<<<512, 256>>>(out);
}

// round 10
// speedup vs baseline: 1.1618x; 1.0434x over previous
#include <cuda_runtime.h>
#include <cstdint>

// ---------------- device-global scratch ----------------
__device__ float g_W1t[512 * 512];      // W_hx^T [n][k] tf32
__device__ float g_Wht[512 * 512];      // W_hh^T [n][k] tf32
__device__ float g_Whh[512 * 512];      // W_hh fp32
__device__ float g_W2[512 * 512];       // W^2 fp32
__device__ float g_W4[512 * 512];       // W^4 fp32
__device__ float g_W8[512 * 512];       // W^8 fp32
__device__ float g_WCt[1024 * 512];     // [W4t ; W8t] tf32 [n][k]
__device__ float g_Wot[512 * 1024];     // W_o^T [n][k] tf32
__device__ float g_bh[512];
__device__ float g_bo[512];
__device__ float g_xr[(size_t)65536 * 512];     // tf32-rounded x [b*256+t][k]
__device__ float g_preh[(size_t)65536 * 512];   // [t*256+b][n] tf32-rounded
__device__ float g_Hall[(size_t)257 * 131072];  // [t][b][n] tf32-rounded
__device__ float g_Q0[(size_t)16384 * 512];
__device__ float g_Q1[(size_t)16384 * 512];
__device__ int g_cnt, g_phase;

// ---------------- helpers ----------------
__device__ __forceinline__ uint32_t smem_u32(const void* p) {
    uint32_t a;
    asm("{ .reg .u64 t; cvta.to.shared.u64 t, %1; cvt.u32.u64 %0, t; }" : "=r"(a) : "l"(p));
    return a;
}
__device__ __forceinline__ float rna_tf32(float x) {
    uint32_t r; asm("cvt.rna.tf32.f32 %0, %1;" : "=r"(r) : "f"(x));
    return __uint_as_float(r);
}
__device__ __forceinline__ int rowmap(int mode, int off, int m) {
    if (mode == 1) return ((m & 255) << 8) | (m >> 8);
    if (mode == 2) return ((m >> 8) << 10) + (off << 8) + (m & 255);
    if (mode == 3) return ((m >> 8) << 9) + (off << 8) + (m & 255);
    return m;
}
__device__ __forceinline__ void mma8(float* c, const uint32_t* a, const uint32_t* b) {
    asm volatile("mma.sync.aligned.m16n8k8.row.col.f32.tf32.tf32.f32 "
        "{%0,%1,%2,%3}, {%4,%5,%6,%7}, {%8,%9}, {%0,%1,%2,%3};"
        : "+f"(c[0]), "+f"(c[1]), "+f"(c[2]), "+f"(c[3])
        : "r"(a[0]), "r"(a[1]), "r"(a[2]), "r"(a[3]), "r"(b[0]), "r"(b[1]));
}
#define CP16(dst, src) asm volatile("cp.async.cg.shared.global [%0], [%1], 16;" :: "r"(dst), "l"(src))
#define LDSM4(r0, r1, r2, r3, addr)                                              \
    asm volatile("ldmatrix.sync.aligned.m8n8.x4.shared.b16 {%0,%1,%2,%3}, [%4];" \
        : "=r"(r0), "=r"(r1), "=r"(r2), "=r"(r3) : "r"(addr))
#define COMMIT() asm volatile("cp.async.commit_group;")
#define WAIT2()  asm volatile("cp.async.wait_group 2;")

// ---------------- prep ----------------
__global__ void prep_kernel(const float* __restrict__ Wh, const float* __restrict__ bh,
                            const float* __restrict__ Wo, const float* __restrict__ bo,
                            const float* __restrict__ h0) {
    int i = blockIdx.x * blockDim.x + threadIdx.x;
    if (i == 0) { g_cnt = 0; g_phase = 0; }
    if (i < 524288) {
        int k = i >> 9, n = i & 511;
        g_Wot[n * 1024 + k] = rna_tf32(Wo[i]);
    }
    if (i < 262144) {
        int k = i >> 9, n = i & 511;
        g_W1t[n * 512 + k] = rna_tf32(Wh[i]);
        float w = Wh[262144 + i];
        g_Whh[i] = w;
        g_Wht[n * 512 + k] = rna_tf32(w);
    }
    if (i < 131072) g_Hall[i] = rna_tf32(h0[i]);
    if (i < 512) { g_bh[i] = bh[i]; g_bo[i] = bo[i]; }
}

__global__ void xr_kernel(const float* __restrict__ x) {
    size_t i = ((size_t)blockIdx.x * blockDim.x + threadIdx.x) * 4;
    float4 v = *(const float4*)(x + i);
    v.x = rna_tf32(v.x); v.y = rna_tf32(v.y);
    v.z = rna_tf32(v.z); v.w = rna_tf32(v.w);
    *(float4*)(g_xr + i) = v;
}

// ------------- fp32 512^3 GEMM (squarings), 32x64 tile, grid(8,16) -------------
__global__ __launch_bounds__(256) void sq512(const float* __restrict__ A,
                                             const float* __restrict__ B,
                                             float* __restrict__ C,
                                             float* __restrict__ Ct) {
    __shared__ float As[16][36];
    __shared__ float Bs[16][64];
    const int tid = threadIdx.x;
    const int bm = blockIdx.y * 32, bn = blockIdx.x * 64;
    const int tx = tid & 15, ty = tid >> 4;
    const int ar = tid >> 3, ac2 = (tid & 7) * 2;
    const int br = tid >> 4, bc4 = (tid & 15) * 4;

    float acc[2][4] = {{0, 0, 0, 0}, {0, 0, 0, 0}};
    for (int k0 = 0; k0 < 512; k0 += 16) {
        float2 va = *(const float2*)(A + (size_t)(bm + ar) * 512 + k0 + ac2);
        float4 vb = *(const float4*)(B + (size_t)(k0 + br) * 512 + bn + bc4);
        __syncthreads();
        As[ac2 + 0][ar] = va.x;
        As[ac2 + 1][ar] = va.y;
        *(float4*)(&Bs[br][bc4]) = vb;
        __syncthreads();
#pragma unroll
        for (int kk = 0; kk < 16; kk++) {
            float a0 = As[kk][ty * 2 + 0], a1 = As[kk][ty * 2 + 1];
#pragma unroll
            for (int j = 0; j < 4; j++) {
                float b = Bs[kk][tx * 4 + j];
                acc[0][j] += a0 * b;
                acc[1][j] += a1 * b;
            }
        }
    }
#pragma unroll
    for (int i = 0; i < 2; i++) {
        int m = bm + ty * 2 + i;
        float4 v = {acc[i][0], acc[i][1], acc[i][2], acc[i][3]};
        *(float4*)(C + (size_t)m * 512 + bn + tx * 4) = v;
        if (Ct) {
#pragma unroll
            for (int j = 0; j < 4; j++)
                Ct[(size_t)(bn + tx * 4 + j) * 512 + m] = rna_tf32(acc[i][j]);
        }
    }
}

// ---------------- tf32 mma GEMM, 128x128 tile, 4-stage pipeline ----------------
// dynamic smem: A = 4 stages x 128x20, B same (81920 B)
// MODE 0: O = rna(A@Bt + bias)  K=512 | MODE 1: sigmoid, A=[xr|Hall-gather], K=1024
// MODE 2: O = rna(A@Bt + Add)   K=512
template <int MODE>
__global__ __launch_bounds__(256, 2) void mma_gemm(
    const float* __restrict__ A0, const float* __restrict__ A1, int amap, int aoff,
    const float* __restrict__ Add, int addmap, int addoff,
    float* __restrict__ O, int omap, int ooff,
    const float* __restrict__ Bt, const float* __restrict__ bias) {
    extern __shared__ float sm[];
    float* Asg = sm;            // 4 x 2560 floats
    float* Bsg = sm + 10240;    // 4 x 2560 floats

    const int tid = threadIdx.x;
    const int lane = tid & 31;
    const int wid = tid >> 5;
    const int wm = (wid >> 2) * 64;
    const int wn = (wid & 3) * 32;
    const int bm = blockIdx.y * 128;
    const int bn = blockIdx.x * 128;
    const int KD = (MODE == 1) ? 1024 : 512;
    const int NIT = KD / 16;

    const int ar1 = tid >> 2, ac = (tid & 3) * 4;

    const float* aP[2];
    const float* aH[2];
#pragma unroll
    for (int h = 0; h < 2; h++) {
        int gm = bm + ar1 + h * 64;
        if (MODE == 1) {
            aP[h] = A0 + (size_t)gm * 512 + ac;
            aH[h] = A1 + (size_t)((((gm & 255) << 8) | (gm >> 8))) * 512 + ac;
        } else {
            aP[h] = A0 + (size_t)rowmap(amap, aoff, gm) * 512 + ac;
        }
    }
    const float* bP = Bt + (size_t)(bn + ar1) * KD + ac;

    auto issue = [&](int it) {
        if (it < NIT) {
            const int k0 = it * 16;
            float* Ast = Asg + (it & 3) * 2560;
            float* Bst = Bsg + (it & 3) * 2560;
#pragma unroll
            for (int h = 0; h < 2; h++) {
                const float* src = (MODE == 1 && k0 >= 512) ? aH[h] + (k0 - 512) : aP[h] + k0;
                CP16(smem_u32(Ast + (ar1 + h * 64) * 20 + ac), src);
                CP16(smem_u32(Bst + (ar1 + h * 64) * 20 + ac), bP + (size_t)h * 64 * KD + k0);
            }
        }
        COMMIT();
    };

    // ldmatrix lane-invariant bases (per stage)
    const int rA = ((lane >> 3) & 1) * 8 + (lane & 7);
    const int cA = ((lane >> 4) & 1) * 4;
    const int rB = ((lane >> 4) & 1) * 8 + (lane & 7);
    const int cB = ((lane >> 3) & 1) * 4;
    uint32_t baseA[4], baseB[4];
#pragma unroll
    for (int s = 0; s < 4; s++) {
        baseA[s] = smem_u32(Asg + s * 2560 + (wm + rA) * 20 + cA);
        baseB[s] = smem_u32(Bsg + s * 2560 + (wn + rB) * 20 + cB);
    }

    float acc[4][4][4];
#pragma unroll
    for (int a = 0; a < 4; a++)
#pragma unroll
        for (int b = 0; b < 4; b++)
#pragma unroll
            for (int c = 0; c < 4; c++) acc[a][b][c] = 0.f;

    issue(0); issue(1); issue(2);
    for (int it = 0; it < NIT; it++) {
        WAIT2();
        __syncthreads();
        issue(it + 3);
        const int buf = it & 3;
#pragma unroll
        for (int kk = 0; kk < 2; kk++) {
            uint32_t af[4][4], bf[2][4];
#pragma unroll
            for (int mf = 0; mf < 4; mf++)
                LDSM4(af[mf][0], af[mf][1], af[mf][2], af[mf][3],
                      baseA[buf] + mf * 1280 + kk * 32);
#pragma unroll
            for (int p = 0; p < 2; p++)
                LDSM4(bf[p][0], bf[p][1], bf[p][2], bf[p][3],
                      baseB[buf] + p * 1280 + kk * 32);
#pragma unroll
            for (int mf = 0; mf < 4; mf++)
#pragma unroll
                for (int p = 0; p < 2; p++) {
                    mma8(acc[mf][2 * p + 0], af[mf], &bf[p][0]);
                    mma8(acc[mf][2 * p + 1], af[mf], &bf[p][2]);
                }
        }
    }

#pragma unroll
    for (int mf = 0; mf < 4; mf++)
#pragma unroll
        for (int nf = 0; nf < 4; nf++) {
            int col = bn + wn + nf * 8 + (lane & 3) * 2;
#pragma unroll
            for (int h = 0; h < 2; h++) {
                int r = bm + wm + mf * 16 + (lane >> 2) + h * 8;
                float c0 = acc[mf][nf][h * 2 + 0];
                float c1 = acc[mf][nf][h * 2 + 1];
                float2 v;
                if (MODE == 2) {
                    const float* ap = Add + (size_t)rowmap(addmap, addoff, r) * 512 + col;
                    v.x = rna_tf32(c0 + ap[0]);
                    v.y = rna_tf32(c1 + ap[1]);
                } else if (MODE == 0) {
                    v.x = rna_tf32(c0 + bias[col]);
                    v.y = rna_tf32(c1 + bias[col + 1]);
                } else {
                    v.x = 1.f / (1.f + __expf(-(c0 + bias[col])));
                    v.y = 1.f / (1.f + __expf(-(c1 + bias[col + 1])));
                }
                *(float2*)(O + (size_t)rowmap(omap, ooff, r) * 512 + col) = v;
            }
        }
}

// ---------------- persistent tensor-core scan, 4-stage pipeline ----------------
// superstep k: C[256x1024] = Hall[8k] @ [W4t ; W8t]
//   left  half: Hall[8k+4] = rna(C_l + Q4[2k])
//   right half: Hall[8k+8] = rna(C_r + Q8[k]);  k==31 -> out tail (fp32)
__device__ __forceinline__ void gbar(int target) {
    __syncthreads();
    if (threadIdx.x == 0) {
        __threadfence();
        int old = atomicAdd(&g_cnt, 1);
        if (old == 63) {
            g_cnt = 0;
            __threadfence();
            atomicExch(&g_phase, target);
        } else {
            while (atomicAdd(&g_phase, 0) < target) {}
        }
    }
    __syncthreads();
}

__global__ __launch_bounds__(256) void scan_kernel(const float* __restrict__ q4,
                                                   const float* __restrict__ q8,
                                                   float* __restrict__ outp) {
    extern __shared__ float sm[];
    float* Asg = sm;           // 4 x 640 floats (32 rows x 20)
    float* Bsg = sm + 2560;    // 4 x 2560 floats
    const int tid = threadIdx.x;
    const int lane = tid & 31;
    const int wid = tid >> 5;
    const int wm = (wid >> 2) * 16;
    const int wn = (wid & 3) * 32;
    const int bn = blockIdx.x * 128;    // over N=1024
    const int bm = blockIdx.y * 32;     // over M=256
    const int aar = tid >> 2, aac = (tid & 3) * 4;
    const int br = tid >> 2, bc = (tid & 3) * 4;
    const float* bP = g_WCt + (size_t)(bn + br) * 512 + bc;

    const int rA = ((lane >> 3) & 1) * 8 + (lane & 7);
    const int cA = ((lane >> 4) & 1) * 4;
    const int rB = ((lane >> 4) & 1) * 8 + (lane & 7);
    const int cB = ((lane >> 3) & 1) * 4;
    uint32_t baseA[4], baseB[4];
#pragma unroll
    for (int s = 0; s < 4; s++) {
        baseA[s] = smem_u32(Asg + s * 640 + (wm + rA) * 20 + cA);
        baseB[s] = smem_u32(Bsg + s * 2560 + (wn + rB) * 20 + cB);
    }

    for (int k = 0; k < 32; k++) {
        const float* hsrc = g_Hall + (size_t)(8 * k) * 131072;

        auto issue = [&](int it) {
            if (it < 32) {
                const int k0 = it * 16;
                float* Ast = Asg + (it & 3) * 640;
                float* Bst = Bsg + (it & 3) * 2560;
                if (tid < 128)
                    CP16(smem_u32(Ast + aar * 20 + aac),
                         hsrc + (size_t)(bm + aar) * 512 + k0 + aac);
#pragma unroll
                for (int h = 0; h < 2; h++)
                    CP16(smem_u32(Bst + (br + h * 64) * 20 + bc),
                         bP + (size_t)h * 64 * 512 + k0);
            }
            COMMIT();
        };

        float acc[4][4];
#pragma unroll
        for (int a = 0; a < 4; a++)
#pragma unroll
            for (int b = 0; b < 4; b++) acc[a][b] = 0.f;

        issue(0); issue(1); issue(2);
        for (int it = 0; it < 32; it++) {
            WAIT2();
            __syncthreads();
            issue(it + 3);
            const int buf = it & 3;
#pragma unroll
            for (int kk = 0; kk < 2; kk++) {
                uint32_t af[4], bf[2][4];
                LDSM4(af[0], af[1], af[2], af[3], baseA[buf] + kk * 32);
#pragma unroll
                for (int p = 0; p < 2; p++)
                    LDSM4(bf[p][0], bf[p][1], bf[p][2], bf[p][3],
                          baseB[buf] + p * 1280 + kk * 32);
#pragma unroll
                for (int p = 0; p < 2; p++) {
                    mma8(acc[2 * p + 0], af, &bf[p][0]);
                    mma8(acc[2 * p + 1], af, &bf[p][2]);
                }
            }
        }

#pragma unroll
        for (int nf = 0; nf < 4; nf++) {
            int col = bn + wn + nf * 8 + (lane & 3) * 2;
#pragma unroll
            for (int h = 0; h < 2; h++) {
                int r = bm + wm + (lane >> 2) + h * 8;
                float c0 = acc[nf][h * 2 + 0];
                float c1 = acc[nf][h * 2 + 1];
                size_t off = (size_t)r * 512;
                if (bn < 512) {
                    const float* p = q4 + (size_t)(2 * k) * 131072 + off + col;
                    float2 v = {rna_tf32(c0 + p[0]), rna_tf32(c1 + p[1])};
                    *(float2*)(g_Hall + (size_t)(8 * k + 4) * 131072 + off + col) = v;
                } else {
                    int c2 = col - 512;
                    const float* p = q8 + (size_t)k * 131072 + off + c2;
                    float f0 = c0 + p[0], f1 = c1 + p[1];
                    float2 v = {rna_tf32(f0), rna_tf32(f1)};
                    *(float2*)(g_Hall + (size_t)(8 * k + 8) * 131072 + off + c2) = v;
                    if (k == 31) {
                        float2 w = {f0, f1};
                        *(float2*)(outp + (size_t)33554432 + off + c2) = w;
                    }
                }
            }
        }
        gbar(k + 1);
    }
}

// ---------------- launch ----------------
extern "C" void kernel_launch(void* const* d_in, const int* in_sizes, int n_in,
                              void* d_out, int out_size) {
    const float* x  = (const float*)d_in[0];
    const float* h0 = (const float*)d_in[1];
    const float* Wh = (const float*)d_in[2];
    const float* bh = (const float*)d_in[3];
    const float* Wo = (const float*)d_in[4];
    const float* bo = (const float*)d_in[5];
    float* out = (float*)d_out;

    float *xr, *preh, *hall, *q0, *q1, *w1t, *wht, *whh, *w2, *w4, *w8, *wct, *wot, *bhp, *bop;
    cudaGetSymbolAddress((void**)&xr, g_xr);
    cudaGetSymbolAddress((void**)&preh, g_preh);
    cudaGetSymbolAddress((void**)&hall, g_Hall);
    cudaGetSymbolAddress((void**)&q0, g_Q0);
    cudaGetSymbolAddress((void**)&q1, g_Q1);
    cudaGetSymbolAddress((void**)&w1t, g_W1t);
    cudaGetSymbolAddress((void**)&wht, g_Wht);
    cudaGetSymbolAddress((void**)&whh, g_Whh);
    cudaGetSymbolAddress((void**)&w2, g_W2);
    cudaGetSymbolAddress((void**)&w4, g_W4);
    cudaGetSymbolAddress((void**)&w8, g_W8);
    cudaGetSymbolAddress((void**)&wct, g_WCt);
    cudaGetSymbolAddress((void**)&wot, g_Wot);
    cudaGetSymbolAddress((void**)&bhp, g_bh);
    cudaGetSymbolAddress((void**)&bop, g_bo);

    const int MMA_SMEM = 81920;
    const int SCAN_SMEM = 51200;
    cudaFuncSetAttribute(mma_gemm<0>, cudaFuncAttributeMaxDynamicSharedMemorySize, MMA_SMEM);
    cudaFuncSetAttribute(mma_gemm<1>, cudaFuncAttributeMaxDynamicSharedMemorySize, MMA_SMEM);
    cudaFuncSetAttribute(mma_gemm<2>, cudaFuncAttributeMaxDynamicSharedMemorySize, MMA_SMEM);
    cudaFuncSetAttribute(scan_kernel, cudaFuncAttributeMaxDynamicSharedMemorySize, SCAN_SMEM);

    prep_kernel<<<2048, 256>>>(Wh, bh, Wo, bo, h0);
    xr_kernel<<<32768, 256>>>(x);
    sq512<<<dim3(8, 16), 256>>>(whh, whh, w2, nullptr);
    sq512<<<dim3(8, 16), 256>>>(w2, w2, w4, wct);             // W4 + W4t(tf32)
    sq512<<<dim3(8, 16), 256>>>(w4, w4, w8, wct + 262144);    // W8 + W8t(tf32)

    // G1: preh[t*256+b] = rna(xr[b][t] @ W_hx + b_h)
    mma_gemm<0><<<dim3(4, 512), 256, MMA_SMEM>>>(xr, nullptr, 1, 0, nullptr, 0, 0,
                                                 preh, 0, 0, w1t, bhp);
    // Horner chunks of 4 -> Q4 (q0)
    mma_gemm<2><<<dim3(4, 128), 256, MMA_SMEM>>>(preh, nullptr, 2, 0, preh, 2, 1,
                                                 q0, 0, 0, wht, nullptr);
    mma_gemm<2><<<dim3(4, 128), 256, MMA_SMEM>>>(q0, nullptr, 0, 0, preh, 2, 2,
                                                 q1, 0, 0, wht, nullptr);
    mma_gemm<2><<<dim3(4, 128), 256, MMA_SMEM>>>(q1, nullptr, 0, 0, preh, 2, 3,
                                                 q0, 0, 0, wht, nullptr);
    // Q8[k] = Q4[2k]@W4 + Q4[2k+1] -> q1  (W4t = first half of WCt)
    mma_gemm<2><<<dim3(4, 64), 256, MMA_SMEM>>>(q0, nullptr, 3, 0, q0, 3, 1,
                                                q1, 0, 0, wct, nullptr);
    // persistent tensor-core scan, 32 supersteps (writes out tail at k=31)
    scan_kernel<<<dim3(8, 8), 256, SCAN_SMEM>>>(q0, q1, out);
    // interior recovery: Hall[4j+i] = rna(Hall[4j+i-1]@W + preh[4j+i-1])
    for (int i = 1; i <= 3; i++)
        mma_gemm<2><<<dim3(4, 128), 256, MMA_SMEM>>>(hall, nullptr, 2, i - 1, preh, 2, i - 1,
                                                     hall, 2, i, wht, nullptr);
    // G2: out[b*256+t] = sigmoid([xr | Hall[t]] @ W_o + b_o)
    mma_gemm<1><<<dim3(4, 512), 256, MMA_SMEM>>>(xr, hall, 0, 0, nullptr, 0, 0,
                                                 out, 0, 0, wot, bop);
}